// round 1
// baseline (speedup 1.0000x reference)
#include <cuda_runtime.h>
#include <math.h>

#define DMODEL 1024
#define DFF    4096
#define NHEADS 16
#define DKV    64
#define BATCH  8
#define SEQ    1024
#define MROWS  (BATCH*SEQ)    // 8192
#define BH     (BATCH*NHEADS) // 128

// ---------------- scratch (no allocations allowed) ----------------
__device__ float g_q[BH*SEQ*DKV];       // [B,H,S,Dk]
__device__ float g_k[BH*SEQ*DKV];
__device__ float g_v[BH*SEQ*DKV];
__device__ float g_ctx[MROWS*DMODEL];   // [B,S,H*Dv]
__device__ float g_tmp[MROWS*DMODEL];   // pre-LN buffer
__device__ float g_ao[MROWS*DMODEL];    // attn_out (post LN1)
__device__ float g_h[(size_t)MROWS*DFF];// FFN hidden

// ---------------- generic SGEMM 128x128x16, 8x8 per thread ----------------
// mode 0: C = A@B + bias
// mode 1: C = A@B + bias, remapped [M,N]->[B,H,S,D]  (for q/k/v)
// mode 2: C = A@B + bias + resid
// mode 3: C = relu(A@B + bias)
__global__ __launch_bounds__(256) void sgemm128(
    const float* __restrict__ A, const float* __restrict__ B,
    const float* __restrict__ bias, const float* __restrict__ resid,
    float* __restrict__ C, int M, int N, int K, int mode)
{
    __shared__ float As[16][128];   // [k][m]
    __shared__ float Bs[16][128];   // [k][n]
    const int tid = threadIdx.x;
    const int bm = blockIdx.y, bn = blockIdx.x;
    const int tx = tid & 15, ty = tid >> 4;

    const int arow = tid >> 1;         // 0..127
    const int acol = (tid & 1) * 8;    // 0 or 8
    const int brow = tid >> 4;         // 0..15
    const int bcol = (tid & 15) * 8;   // 0..120

    const float* Ab = A + (size_t)(bm*128 + arow)*K + acol;
    const float* Bb = B + (size_t)brow*N + (size_t)bn*128 + bcol;

    float acc[8][8];
    #pragma unroll
    for (int i = 0; i < 8; i++)
        #pragma unroll
        for (int j = 0; j < 8; j++) acc[i][j] = 0.f;

    for (int k0 = 0; k0 < K; k0 += 16) {
        float4 a0 = *(const float4*)(Ab + k0);
        float4 a1 = *(const float4*)(Ab + k0 + 4);
        As[acol+0][arow] = a0.x; As[acol+1][arow] = a0.y;
        As[acol+2][arow] = a0.z; As[acol+3][arow] = a0.w;
        As[acol+4][arow] = a1.x; As[acol+5][arow] = a1.y;
        As[acol+6][arow] = a1.z; As[acol+7][arow] = a1.w;
        const float* bp = Bb + (size_t)k0 * N;
        *(float4*)&Bs[brow][bcol]     = *(const float4*)(bp);
        *(float4*)&Bs[brow][bcol + 4] = *(const float4*)(bp + 4);
        __syncthreads();
        #pragma unroll
        for (int kk = 0; kk < 16; kk++) {
            float4 av0 = *(const float4*)&As[kk][ty*8];
            float4 av1 = *(const float4*)&As[kk][ty*8 + 4];
            float4 bv0 = *(const float4*)&Bs[kk][tx*8];
            float4 bv1 = *(const float4*)&Bs[kk][tx*8 + 4];
            float a[8] = {av0.x,av0.y,av0.z,av0.w,av1.x,av1.y,av1.z,av1.w};
            float b[8] = {bv0.x,bv0.y,bv0.z,bv0.w,bv1.x,bv1.y,bv1.z,bv1.w};
            #pragma unroll
            for (int i = 0; i < 8; i++)
                #pragma unroll
                for (int j = 0; j < 8; j++)
                    acc[i][j] = fmaf(a[i], b[j], acc[i][j]);
        }
        __syncthreads();
    }

    #pragma unroll
    for (int i = 0; i < 8; i++) {
        const int m = bm*128 + ty*8 + i;
        #pragma unroll
        for (int j = 0; j < 8; j++) {
            const int n = bn*128 + tx*8 + j;
            float v = acc[i][j] + bias[n];
            if (mode == 2) v += resid[(size_t)m*N + n];
            else if (mode == 3) v = fmaxf(v, 0.f);
            if (mode == 1) {
                const int h = n >> 6, d = n & 63;
                const int bb = m >> 10, s = m & 1023;
                C[(((size_t)(bb*NHEADS + h))*SEQ + s)*DKV + d] = v;
            } else {
                C[(size_t)m*N + n] = v;
            }
        }
    }
}

// ---------------- attention scores: attn[bz] = q[bz] @ k[bz]^T * 0.125 ----------------
__global__ __launch_bounds__(256) void attn_scores(
    const float* __restrict__ q, const float* __restrict__ k,
    const unsigned char* __restrict__ mask, float* __restrict__ attn)
{
    __shared__ float Qs[64][64];  // [dk][m]
    __shared__ float Ks[64][64];  // [dk][n]
    const int bz = blockIdx.z;           // b*16+h
    const int b  = bz >> 4;
    const float* qb = q + (size_t)bz*SEQ*DKV + (size_t)blockIdx.y*64*DKV;
    const float* kb = k + (size_t)bz*SEQ*DKV + (size_t)blockIdx.x*64*DKV;
    const int tid = threadIdx.x;
    const int row = tid >> 2;            // 0..63
    const int cg  = (tid & 3) * 16;      // 0,16,32,48
    #pragma unroll
    for (int c = 0; c < 16; c += 4) {
        float4 qv = *(const float4*)(qb + (size_t)row*DKV + cg + c);
        Qs[cg+c+0][row] = qv.x; Qs[cg+c+1][row] = qv.y;
        Qs[cg+c+2][row] = qv.z; Qs[cg+c+3][row] = qv.w;
        float4 kv = *(const float4*)(kb + (size_t)row*DKV + cg + c);
        Ks[cg+c+0][row] = kv.x; Ks[cg+c+1][row] = kv.y;
        Ks[cg+c+2][row] = kv.z; Ks[cg+c+3][row] = kv.w;
    }
    __syncthreads();
    const int tx = tid & 15, ty = tid >> 4;
    float acc[4][4];
    #pragma unroll
    for (int i = 0; i < 4; i++)
        #pragma unroll
        for (int j = 0; j < 4; j++) acc[i][j] = 0.f;
    #pragma unroll 8
    for (int kk = 0; kk < 64; kk++) {
        float4 a4 = *(const float4*)&Qs[kk][ty*4];
        float4 b4 = *(const float4*)&Ks[kk][tx*4];
        float a[4] = {a4.x,a4.y,a4.z,a4.w};
        float bb4[4] = {b4.x,b4.y,b4.z,b4.w};
        #pragma unroll
        for (int i = 0; i < 4; i++)
            #pragma unroll
            for (int j = 0; j < 4; j++)
                acc[i][j] = fmaf(a[i], bb4[j], acc[i][j]);
    }
    const unsigned char* mb = mask + (size_t)b*SEQ*SEQ;
    float* ab = attn + (size_t)bz*SEQ*SEQ;
    #pragma unroll
    for (int i = 0; i < 4; i++) {
        const int qr = blockIdx.y*64 + ty*4 + i;
        #pragma unroll
        for (int j = 0; j < 4; j++) {
            const int kc = blockIdx.x*64 + tx*4 + j;
            float v = acc[i][j] * 0.125f;
            if (mb[(size_t)qr*SEQ + kc]) v = -1e9f;
            ab[(size_t)qr*SEQ + kc] = v;
        }
    }
}

// ---------------- row softmax over 1024, in place ----------------
__global__ __launch_bounds__(256) void softmax_rows(float* __restrict__ attn)
{
    __shared__ float sbuf[256];
    const size_t row = blockIdx.x;
    float* p = attn + row * 1024;
    const int tid = threadIdx.x;
    float4 v = *(const float4*)(p + tid*4);
    float m = fmaxf(fmaxf(v.x, v.y), fmaxf(v.z, v.w));
    sbuf[tid] = m; __syncthreads();
    for (int s = 128; s > 0; s >>= 1) {
        if (tid < s) sbuf[tid] = fmaxf(sbuf[tid], sbuf[tid+s]);
        __syncthreads();
    }
    m = sbuf[0]; __syncthreads();
    v.x = __expf(v.x - m); v.y = __expf(v.y - m);
    v.z = __expf(v.z - m); v.w = __expf(v.w - m);
    sbuf[tid] = v.x + v.y + v.z + v.w; __syncthreads();
    for (int s = 128; s > 0; s >>= 1) {
        if (tid < s) sbuf[tid] += sbuf[tid+s];
        __syncthreads();
    }
    const float inv = 1.f / sbuf[0];
    v.x *= inv; v.y *= inv; v.z *= inv; v.w *= inv;
    *(float4*)(p + tid*4) = v;
}

// ---------------- ctx[bz] = attn[bz] @ v[bz]  -> [B,S,H*Dv] ----------------
__global__ __launch_bounds__(256) void attn_ctx(
    const float* __restrict__ attn, const float* __restrict__ v,
    float* __restrict__ ctx)
{
    __shared__ float As[64][64];  // [kk][m]
    __shared__ float Vs[64][64];  // [kk][d]
    const int bz = blockIdx.y;          // b*16+h
    const int mt = blockIdx.x;          // 0..15
    const float* ab = attn + (size_t)bz*SEQ*SEQ + (size_t)mt*64*SEQ;
    const float* vb = v + (size_t)bz*SEQ*DKV;
    const int tid = threadIdx.x;
    const int row = tid >> 2;           // 0..63
    const int cg  = (tid & 3) * 16;
    const int tx = tid & 15, ty = tid >> 4;
    float acc[4][4];
    #pragma unroll
    for (int i = 0; i < 4; i++)
        #pragma unroll
        for (int j = 0; j < 4; j++) acc[i][j] = 0.f;

    for (int k0 = 0; k0 < SEQ; k0 += 64) {
        #pragma unroll
        for (int c = 0; c < 16; c += 4) {
            float4 av = *(const float4*)(ab + (size_t)row*SEQ + k0 + cg + c);
            As[cg+c+0][row] = av.x; As[cg+c+1][row] = av.y;
            As[cg+c+2][row] = av.z; As[cg+c+3][row] = av.w;
            *(float4*)&Vs[row][cg + c] =
                *(const float4*)(vb + (size_t)(k0+row)*DKV + cg + c);
        }
        __syncthreads();
        #pragma unroll 8
        for (int kk = 0; kk < 64; kk++) {
            float4 a4 = *(const float4*)&As[kk][ty*4];
            float4 b4 = *(const float4*)&Vs[kk][tx*4];
            float a[4] = {a4.x,a4.y,a4.z,a4.w};
            float bb4[4] = {b4.x,b4.y,b4.z,b4.w};
            #pragma unroll
            for (int i = 0; i < 4; i++)
                #pragma unroll
                for (int j = 0; j < 4; j++)
                    acc[i][j] = fmaf(a[i], bb4[j], acc[i][j]);
        }
        __syncthreads();
    }
    const int b = bz >> 4, h = bz & 15;
    float* cb = ctx + (size_t)b*SEQ*DMODEL + (size_t)h*DKV;
    #pragma unroll
    for (int i = 0; i < 4; i++) {
        const int s = mt*64 + ty*4 + i;
        #pragma unroll
        for (int j = 0; j < 4; j++)
            cb[(size_t)s*DMODEL + tx*4 + j] = acc[i][j];
    }
}

// ---------------- layernorm over last dim 1024 ----------------
__global__ __launch_bounds__(256) void layernorm_rows(
    const float* __restrict__ in, const float* __restrict__ g,
    const float* __restrict__ bta, float* __restrict__ out)
{
    __shared__ float s1[256], s2[256];
    const size_t row = blockIdx.x;
    const float* p = in + row * DMODEL;
    const int tid = threadIdx.x;
    float4 v = *(const float4*)(p + tid*4);
    s1[tid] = v.x + v.y + v.z + v.w;
    s2[tid] = v.x*v.x + v.y*v.y + v.z*v.z + v.w*v.w;
    __syncthreads();
    for (int st = 128; st > 0; st >>= 1) {
        if (tid < st) { s1[tid] += s1[tid+st]; s2[tid] += s2[tid+st]; }
        __syncthreads();
    }
    const float mu  = s1[0] * (1.f/DMODEL);
    const float var = s2[0] * (1.f/DMODEL) - mu*mu;
    const float rs  = rsqrtf(var + 1e-5f);
    float4 gv = *(const float4*)(g + tid*4);
    float4 bv = *(const float4*)(bta + tid*4);
    float4 o;
    o.x = (v.x - mu)*rs*gv.x + bv.x;
    o.y = (v.y - mu)*rs*gv.y + bv.y;
    o.z = (v.z - mu)*rs*gv.z + bv.z;
    o.w = (v.w - mu)*rs*gv.w + bv.w;
    *(float4*)(out + row*DMODEL + tid*4) = o;
}

// ---------------- launch ----------------
extern "C" void kernel_launch(void* const* d_in, const int* in_sizes, int n_in,
                              void* d_out, int out_size)
{
    const float* x    = (const float*)d_in[0];
    const unsigned char* mask = (const unsigned char*)d_in[1];
    const float* Wq = (const float*)d_in[2];  const float* bq = (const float*)d_in[3];
    const float* Wk = (const float*)d_in[4];  const float* bk = (const float*)d_in[5];
    const float* Wv = (const float*)d_in[6];  const float* bv = (const float*)d_in[7];
    const float* Wo = (const float*)d_in[8];  const float* bo = (const float*)d_in[9];
    const float* ln1g = (const float*)d_in[10]; const float* ln1b = (const float*)d_in[11];
    const float* W1 = (const float*)d_in[12]; const float* b1 = (const float*)d_in[13];
    const float* W2 = (const float*)d_in[14]; const float* b2 = (const float*)d_in[15];
    const float* ln2g = (const float*)d_in[16]; const float* ln2b = (const float*)d_in[17];

    float* out = (float*)d_out;
    float* ffn_out = out;                                    // [B,S,D]
    float* attn    = out + (size_t)MROWS * DMODEL;           // [B,H,S,S]

    float *qp, *kp, *vp, *ctxp, *tmpp, *aop, *hp;
    cudaGetSymbolAddress((void**)&qp,   g_q);
    cudaGetSymbolAddress((void**)&kp,   g_k);
    cudaGetSymbolAddress((void**)&vp,   g_v);
    cudaGetSymbolAddress((void**)&ctxp, g_ctx);
    cudaGetSymbolAddress((void**)&tmpp, g_tmp);
    cudaGetSymbolAddress((void**)&aop,  g_ao);
    cudaGetSymbolAddress((void**)&hp,   g_h);

    // QKV projections -> [B,H,S,Dk]
    sgemm128<<<dim3(8, 64), 256>>>(x, Wq, bq, nullptr, qp, MROWS, DMODEL, DMODEL, 1);
    sgemm128<<<dim3(8, 64), 256>>>(x, Wk, bk, nullptr, kp, MROWS, DMODEL, DMODEL, 1);
    sgemm128<<<dim3(8, 64), 256>>>(x, Wv, bv, nullptr, vp, MROWS, DMODEL, DMODEL, 1);

    // scores + mask -> attn region of d_out, then softmax in place
    attn_scores<<<dim3(16, 16, BH), 256>>>(qp, kp, mask, attn);
    softmax_rows<<<BH * SEQ, 256>>>(attn);

    // ctx = attn @ v -> [B,S,H*Dv]
    attn_ctx<<<dim3(16, BH), 256>>>(attn, vp, ctxp);

    // out proj + residual, LN1
    sgemm128<<<dim3(8, 64), 256>>>(ctxp, Wo, bo, x, tmpp, MROWS, DMODEL, DMODEL, 2);
    layernorm_rows<<<MROWS, 256>>>(tmpp, ln1g, ln1b, aop);

    // FFN
    sgemm128<<<dim3(32, 64), 256>>>(aop, W1, b1, nullptr, hp, MROWS, DFF, DMODEL, 3);
    sgemm128<<<dim3(8, 64), 256>>>(hp, W2, b2, aop, tmpp, MROWS, DMODEL, DFF, 2);
    layernorm_rows<<<MROWS, 256>>>(tmpp, ln2g, ln2b, ffn_out);
}

// round 2
// speedup vs baseline: 1.9931x; 1.9931x over previous
#include <cuda_runtime.h>
#include <math.h>

#define DMODEL 1024
#define DFF    4096
#define NHEADS 16
#define DKV    64
#define BATCH  8
#define SEQ    1024
#define MROWS  (BATCH*SEQ)    // 8192
#define BH     (BATCH*NHEADS) // 128

// ---------------- scratch (no allocations allowed) ----------------
__device__ float g_q[BH*SEQ*DKV];       // [B,H,S,Dk]
__device__ float g_k[BH*SEQ*DKV];
__device__ float g_v[BH*SEQ*DKV];
__device__ float g_ctx[MROWS*DMODEL];   // [B,S,H*Dv]
__device__ float g_tmp[MROWS*DMODEL];   // pre-LN buffer
__device__ float g_ao[MROWS*DMODEL];    // attn_out (post LN1)
__device__ float g_h[(size_t)MROWS*DFF];// FFN hidden

// ---------------- helpers ----------------
__device__ __forceinline__ unsigned f2tf(float x) {
    unsigned u;
    asm("cvt.rna.tf32.f32 %0, %1;" : "=r"(u) : "f"(x));
    return u;
}

__device__ __forceinline__ void mma_tf32(float* c, const unsigned* a, const unsigned* b) {
    asm volatile(
        "mma.sync.aligned.m16n8k8.row.col.f32.tf32.tf32.f32 "
        "{%0,%1,%2,%3},{%4,%5,%6,%7},{%8,%9},{%0,%1,%2,%3};"
        : "+f"(c[0]), "+f"(c[1]), "+f"(c[2]), "+f"(c[3])
        : "r"(a[0]), "r"(a[1]), "r"(a[2]), "r"(a[3]), "r"(b[0]), "r"(b[1]));
}

// modes: 1 qkv-remap, 2 +resid, 3 relu, 4 scores(scale+mask), 5 ctx-remap
// Block tile: 128 x BN x 16.  8 warps (2 m x 4 n), warp tile 64 x (BN/4).
template<int BN, int MODE, bool TRANSB>
__global__ void __launch_bounds__(256, 2) gemm_tc(
    const float* __restrict__ A, const float* __restrict__ B,
    const float* __restrict__ bias, const float* __restrict__ resid,
    const unsigned char* __restrict__ mask,
    float* __restrict__ C, int M, int N, int K,
    long long sA, long long sB, long long sC)
{
    constexpr int NT = BN / 32;     // n atoms per warp (8-wide)
    constexpr int WN = BN / 4;      // warp n extent
    __shared__ unsigned As[2][16][132];
    __shared__ unsigned Bs[2][16][BN + 4];

    const int tid = threadIdx.x;
    const int bm = blockIdx.y, bn = blockIdx.x, bz = blockIdx.z;
    A += (long long)bz * sA;
    B += (long long)bz * sB;
    C += (long long)bz * sC;

    const int lane = tid & 31, wid = tid >> 5;
    const int warpM = wid >> 2, warpN = wid & 3;
    const int g = lane >> 2, t = lane & 3;

    // global fetch bases
    const float* Abase = A + (size_t)(bm * 128 + (tid >> 1)) * K + ((tid & 1) * 8);
    const float* Bbase;
    if (TRANSB) {
        Bbase = B + (size_t)(bn * 128 + (tid >> 1)) * K + ((tid & 1) * 8);
    } else if (BN == 128) {
        Bbase = B + (size_t)(tid >> 4) * N + bn * 128 + ((tid & 15) * 8);
    } else {
        Bbase = B + (size_t)(tid >> 4) * N + bn * 64 + ((tid & 15) * 4);
    }

    float fa[8], fb[8];
    float acc[4][NT][4];
    #pragma unroll
    for (int i = 0; i < 4; i++)
        #pragma unroll
        for (int j = 0; j < NT; j++)
            #pragma unroll
            for (int r = 0; r < 4; r++) acc[i][j][r] = 0.f;

    const int nch = K >> 4;

    // ---- fetch chunk 0 ----
    {
        const float* p = Abase;
        float4 u = *(const float4*)p, v = *(const float4*)(p + 4);
        fa[0]=u.x; fa[1]=u.y; fa[2]=u.z; fa[3]=u.w;
        fa[4]=v.x; fa[5]=v.y; fa[6]=v.z; fa[7]=v.w;
        if (TRANSB) {
            const float* q = Bbase;
            float4 a = *(const float4*)q, b = *(const float4*)(q + 4);
            fb[0]=a.x; fb[1]=a.y; fb[2]=a.z; fb[3]=a.w;
            fb[4]=b.x; fb[5]=b.y; fb[6]=b.z; fb[7]=b.w;
        } else if (BN == 128) {
            const float* q = Bbase;
            float4 a = *(const float4*)q, b = *(const float4*)(q + 4);
            fb[0]=a.x; fb[1]=a.y; fb[2]=a.z; fb[3]=a.w;
            fb[4]=b.x; fb[5]=b.y; fb[6]=b.z; fb[7]=b.w;
        } else {
            float4 a = *(const float4*)Bbase;
            fb[0]=a.x; fb[1]=a.y; fb[2]=a.z; fb[3]=a.w;
        }
    }
    // store chunk 0 to stage 0
    {
        const int r = tid >> 1, c0 = (tid & 1) * 8;
        #pragma unroll
        for (int c = 0; c < 8; c++) As[0][c0 + c][r] = f2tf(fa[c]);
        if (TRANSB) {
            const int br = tid >> 1, bc0 = (tid & 1) * 8;
            #pragma unroll
            for (int c = 0; c < 8; c++) Bs[0][bc0 + c][br] = f2tf(fb[c]);
        } else if (BN == 128) {
            const int br = tid >> 4, bc0 = (tid & 15) * 8;
            #pragma unroll
            for (int c = 0; c < 8; c++) Bs[0][br][bc0 + c] = f2tf(fb[c]);
        } else {
            const int br = tid >> 4, bc0 = (tid & 15) * 4;
            #pragma unroll
            for (int c = 0; c < 4; c++) Bs[0][br][bc0 + c] = f2tf(fb[c]);
        }
    }
    __syncthreads();

    for (int ch = 0; ch < nch; ch++) {
        const int cur = ch & 1, nxt = cur ^ 1;
        const bool more = (ch + 1 < nch);
        if (more) {
            const float* p = Abase + (ch + 1) * 16;
            float4 u = *(const float4*)p, v = *(const float4*)(p + 4);
            fa[0]=u.x; fa[1]=u.y; fa[2]=u.z; fa[3]=u.w;
            fa[4]=v.x; fa[5]=v.y; fa[6]=v.z; fa[7]=v.w;
            if (TRANSB) {
                const float* q = Bbase + (ch + 1) * 16;
                float4 a = *(const float4*)q, b = *(const float4*)(q + 4);
                fb[0]=a.x; fb[1]=a.y; fb[2]=a.z; fb[3]=a.w;
                fb[4]=b.x; fb[5]=b.y; fb[6]=b.z; fb[7]=b.w;
            } else if (BN == 128) {
                const float* q = Bbase + (size_t)(ch + 1) * 16 * N;
                float4 a = *(const float4*)q, b = *(const float4*)(q + 4);
                fb[0]=a.x; fb[1]=a.y; fb[2]=a.z; fb[3]=a.w;
                fb[4]=b.x; fb[5]=b.y; fb[6]=b.z; fb[7]=b.w;
            } else {
                const float* q = Bbase + (size_t)(ch + 1) * 16 * N;
                float4 a = *(const float4*)q;
                fb[0]=a.x; fb[1]=a.y; fb[2]=a.z; fb[3]=a.w;
            }
        }

        // compute on stage cur
        #pragma unroll
        for (int ks = 0; ks < 2; ks++) {
            const int kk = ks * 8;
            unsigned af[4][4], bf[NT][2];
            #pragma unroll
            for (int mt = 0; mt < 4; mt++) {
                const int mb = warpM * 64 + mt * 16 + g;
                af[mt][0] = As[cur][kk + t][mb];
                af[mt][1] = As[cur][kk + t][mb + 8];
                af[mt][2] = As[cur][kk + t + 4][mb];
                af[mt][3] = As[cur][kk + t + 4][mb + 8];
            }
            #pragma unroll
            for (int nt = 0; nt < NT; nt++) {
                const int nb = warpN * WN + nt * 8 + g;
                bf[nt][0] = Bs[cur][kk + t][nb];
                bf[nt][1] = Bs[cur][kk + t + 4][nb];
            }
            #pragma unroll
            for (int mt = 0; mt < 4; mt++)
                #pragma unroll
                for (int nt = 0; nt < NT; nt++)
                    mma_tf32(acc[mt][nt], af[mt], bf[nt]);
        }

        if (more) {
            const int r = tid >> 1, c0 = (tid & 1) * 8;
            #pragma unroll
            for (int c = 0; c < 8; c++) As[nxt][c0 + c][r] = f2tf(fa[c]);
            if (TRANSB) {
                const int br = tid >> 1, bc0 = (tid & 1) * 8;
                #pragma unroll
                for (int c = 0; c < 8; c++) Bs[nxt][bc0 + c][br] = f2tf(fb[c]);
            } else if (BN == 128) {
                const int br = tid >> 4, bc0 = (tid & 15) * 8;
                #pragma unroll
                for (int c = 0; c < 8; c++) Bs[nxt][br][bc0 + c] = f2tf(fb[c]);
            } else {
                const int br = tid >> 4, bc0 = (tid & 15) * 4;
                #pragma unroll
                for (int c = 0; c < 4; c++) Bs[nxt][br][bc0 + c] = f2tf(fb[c]);
            }
        }
        __syncthreads();
    }

    // ---- epilogue ----
    #pragma unroll
    for (int mt = 0; mt < 4; mt++) {
        const int r0 = bm * 128 + warpM * 64 + mt * 16 + g;
        const int r1 = r0 + 8;
        #pragma unroll
        for (int nt = 0; nt < NT; nt++) {
            const int c = bn * BN + warpN * WN + nt * 8 + 2 * t;
            float2 lo = make_float2(acc[mt][nt][0], acc[mt][nt][1]);  // row r0
            float2 hi = make_float2(acc[mt][nt][2], acc[mt][nt][3]);  // row r1

            if (MODE == 1 || MODE == 2 || MODE == 3) {
                const float2 bv = *(const float2*)(bias + c);
                lo.x += bv.x; lo.y += bv.y; hi.x += bv.x; hi.y += bv.y;
            }
            if (MODE == 2) {
                const float2 q0 = *(const float2*)(resid + (size_t)r0 * N + c);
                const float2 q1 = *(const float2*)(resid + (size_t)r1 * N + c);
                lo.x += q0.x; lo.y += q0.y; hi.x += q1.x; hi.y += q1.y;
            }
            if (MODE == 3) {
                lo.x = fmaxf(lo.x, 0.f); lo.y = fmaxf(lo.y, 0.f);
                hi.x = fmaxf(hi.x, 0.f); hi.y = fmaxf(hi.y, 0.f);
            }

            if (MODE == 1) {
                // [M,N] -> [B,H,S,D]
                const int h = c >> 6, d = c & 63;
                const int bb0 = r0 >> 10, s0 = r0 & 1023;
                const int bb1 = r1 >> 10, s1 = r1 & 1023;
                *(float2*)(C + (((size_t)(bb0*NHEADS + h))*SEQ + s0)*DKV + d) = lo;
                *(float2*)(C + (((size_t)(bb1*NHEADS + h))*SEQ + s1)*DKV + d) = hi;
            } else if (MODE == 4) {
                const unsigned char* mb = mask + (size_t)(bz >> 4) * SEQ * SEQ;
                lo.x *= 0.125f; lo.y *= 0.125f; hi.x *= 0.125f; hi.y *= 0.125f;
                if (mb[(size_t)r0*SEQ + c])     lo.x = -1e9f;
                if (mb[(size_t)r0*SEQ + c + 1]) lo.y = -1e9f;
                if (mb[(size_t)r1*SEQ + c])     hi.x = -1e9f;
                if (mb[(size_t)r1*SEQ + c + 1]) hi.y = -1e9f;
                *(float2*)(C + (size_t)r0 * N + c) = lo;
                *(float2*)(C + (size_t)r1 * N + c) = hi;
            } else if (MODE == 5) {
                // C row = s within SEQ, col = d; out [B,S,H*Dv]
                const int b = bz >> 4, h = bz & 15;
                *(float2*)(C + ((size_t)b*SEQ + r0)*DMODEL + h*DKV + c) = lo;
                *(float2*)(C + ((size_t)b*SEQ + r1)*DMODEL + h*DKV + c) = hi;
            } else {
                *(float2*)(C + (size_t)r0 * N + c) = lo;
                *(float2*)(C + (size_t)r1 * N + c) = hi;
            }
        }
    }
}

// ---------------- row softmax over 1024, in place ----------------
__global__ __launch_bounds__(256) void softmax_rows(float* __restrict__ attn)
{
    __shared__ float sbuf[256];
    const size_t row = blockIdx.x;
    float* p = attn + row * 1024;
    const int tid = threadIdx.x;
    float4 v = *(const float4*)(p + tid*4);
    float m = fmaxf(fmaxf(v.x, v.y), fmaxf(v.z, v.w));
    sbuf[tid] = m; __syncthreads();
    for (int s = 128; s > 0; s >>= 1) {
        if (tid < s) sbuf[tid] = fmaxf(sbuf[tid], sbuf[tid+s]);
        __syncthreads();
    }
    m = sbuf[0]; __syncthreads();
    v.x = __expf(v.x - m); v.y = __expf(v.y - m);
    v.z = __expf(v.z - m); v.w = __expf(v.w - m);
    sbuf[tid] = v.x + v.y + v.z + v.w; __syncthreads();
    for (int s = 128; s > 0; s >>= 1) {
        if (tid < s) sbuf[tid] += sbuf[tid+s];
        __syncthreads();
    }
    const float inv = 1.f / sbuf[0];
    v.x *= inv; v.y *= inv; v.z *= inv; v.w *= inv;
    *(float4*)(p + tid*4) = v;
}

// ---------------- layernorm over last dim 1024 ----------------
__global__ __launch_bounds__(256) void layernorm_rows(
    const float* __restrict__ in, const float* __restrict__ g,
    const float* __restrict__ bta, float* __restrict__ out)
{
    __shared__ float s1[256], s2[256];
    const size_t row = blockIdx.x;
    const float* p = in + row * DMODEL;
    const int tid = threadIdx.x;
    float4 v = *(const float4*)(p + tid*4);
    s1[tid] = v.x + v.y + v.z + v.w;
    s2[tid] = v.x*v.x + v.y*v.y + v.z*v.z + v.w*v.w;
    __syncthreads();
    for (int st = 128; st > 0; st >>= 1) {
        if (tid < st) { s1[tid] += s1[tid+st]; s2[tid] += s2[tid+st]; }
        __syncthreads();
    }
    const float mu  = s1[0] * (1.f/DMODEL);
    const float var = s2[0] * (1.f/DMODEL) - mu*mu;
    const float rs  = rsqrtf(var + 1e-5f);
    float4 gv = *(const float4*)(g + tid*4);
    float4 bv = *(const float4*)(bta + tid*4);
    float4 o;
    o.x = (v.x - mu)*rs*gv.x + bv.x;
    o.y = (v.y - mu)*rs*gv.y + bv.y;
    o.z = (v.z - mu)*rs*gv.z + bv.z;
    o.w = (v.w - mu)*rs*gv.w + bv.w;
    *(float4*)(out + row*DMODEL + tid*4) = o;
}

// ---------------- launch ----------------
extern "C" void kernel_launch(void* const* d_in, const int* in_sizes, int n_in,
                              void* d_out, int out_size)
{
    const float* x    = (const float*)d_in[0];
    const unsigned char* mask = (const unsigned char*)d_in[1];
    const float* Wq = (const float*)d_in[2];  const float* bq = (const float*)d_in[3];
    const float* Wk = (const float*)d_in[4];  const float* bk = (const float*)d_in[5];
    const float* Wv = (const float*)d_in[6];  const float* bv = (const float*)d_in[7];
    const float* Wo = (const float*)d_in[8];  const float* bo = (const float*)d_in[9];
    const float* ln1g = (const float*)d_in[10]; const float* ln1b = (const float*)d_in[11];
    const float* W1 = (const float*)d_in[12]; const float* b1 = (const float*)d_in[13];
    const float* W2 = (const float*)d_in[14]; const float* b2 = (const float*)d_in[15];
    const float* ln2g = (const float*)d_in[16]; const float* ln2b = (const float*)d_in[17];

    float* out = (float*)d_out;
    float* ffn_out = out;                                    // [B,S,D]
    float* attn    = out + (size_t)MROWS * DMODEL;           // [B,H,S,S]

    float *qp, *kp, *vp, *ctxp, *tmpp, *aop, *hp;
    cudaGetSymbolAddress((void**)&qp,   g_q);
    cudaGetSymbolAddress((void**)&kp,   g_k);
    cudaGetSymbolAddress((void**)&vp,   g_v);
    cudaGetSymbolAddress((void**)&ctxp, g_ctx);
    cudaGetSymbolAddress((void**)&tmpp, g_tmp);
    cudaGetSymbolAddress((void**)&aop,  g_ao);
    cudaGetSymbolAddress((void**)&hp,   g_h);

    // QKV projections -> [B,H,S,Dk]
    gemm_tc<128,1,false><<<dim3(8,64,1),256>>>(x, Wq, bq, nullptr, nullptr, qp, MROWS, DMODEL, DMODEL, 0,0,0);
    gemm_tc<128,1,false><<<dim3(8,64,1),256>>>(x, Wk, bk, nullptr, nullptr, kp, MROWS, DMODEL, DMODEL, 0,0,0);
    gemm_tc<128,1,false><<<dim3(8,64,1),256>>>(x, Wv, bv, nullptr, nullptr, vp, MROWS, DMODEL, DMODEL, 0,0,0);

    // scores: q @ k^T * 0.125 + mask -> attn, then softmax in place
    gemm_tc<128,4,true><<<dim3(8,8,BH),256>>>(qp, kp, nullptr, nullptr, mask, attn,
                                              SEQ, SEQ, DKV,
                                              (long long)SEQ*DKV, (long long)SEQ*DKV, (long long)SEQ*SEQ);
    softmax_rows<<<BH * SEQ, 256>>>(attn);

    // ctx = attn @ v -> [B,S,H*Dv]
    gemm_tc<64,5,false><<<dim3(1,8,BH),256>>>(attn, vp, nullptr, nullptr, nullptr, ctxp,
                                              SEQ, DKV, SEQ,
                                              (long long)SEQ*SEQ, (long long)SEQ*DKV, 0);

    // out proj + residual, LN1
    gemm_tc<128,2,false><<<dim3(8,64,1),256>>>(ctxp, Wo, bo, x, nullptr, tmpp, MROWS, DMODEL, DMODEL, 0,0,0);
    layernorm_rows<<<MROWS, 256>>>(tmpp, ln1g, ln1b, aop);

    // FFN
    gemm_tc<128,3,false><<<dim3(32,64,1),256>>>(aop, W1, b1, nullptr, nullptr, hp, MROWS, DFF, DMODEL, 0,0,0);
    gemm_tc<128,2,false><<<dim3(8,64,1),256>>>(hp, W2, b2, aop, nullptr, tmpp, MROWS, DMODEL, DFF, 0,0,0);
    layernorm_rows<<<MROWS, 256>>>(tmpp, ln2g, ln2b, ffn_out);
}